// round 15
// baseline (speedup 1.0000x reference)
#include <cuda_runtime.h>
#include <cstdint>

#define DIMK 1024
#define BSZ  2
#define SEQ  4096
#define H    16
#define HD   64
#define M_TOT (BSZ * SEQ)   // 8192

// ---------------------------------------------------------------------------
// Scratch (allocation-free). tf32 bit patterns as u32. All k-dimension buffers
// use perm16(k) = ((k&3)<<2)|((k&4)>>2)|(((k&8)>>3)<<1) within each 16-group:
// thread t's fragment cols {t,t+4,t+8,t+12} (two mma k-steps) become one
// aligned uint4 -> LDS.128.
// ---------------------------------------------------------------------------
__device__ uint32_t g_q[(size_t)BSZ * H * SEQ * HD];      // d perm16
__device__ uint32_t g_k[(size_t)BSZ * H * SEQ * HD];      // d perm16
__device__ uint32_t g_v[(size_t)BSZ * H * SEQ * HD];      // unpermuted
__device__ uint32_t g_att[(size_t)BSZ * SEQ * DIMK];      // d perm16
__device__ uint32_t g_x32[(size_t)M_TOT * DIMK];          // k perm16
__device__ uint32_t g_w32[4][(size_t)DIMK * DIMK];        // k perm16

__device__ __forceinline__ int perm16(int k) {
    return ((k & 3) << 2) | ((k & 4) >> 2) | (((k & 8) >> 3) << 1);
}

__device__ __forceinline__ uint32_t f32_tf32(float f) {
    uint32_t r; asm("cvt.rna.tf32.f32 %0, %1;" : "=r"(r) : "f"(f)); return r;
}
__device__ __forceinline__ float ex2f(float x) {
    float r; asm("ex2.approx.f32 %0, %1;" : "=f"(r) : "f"(x)); return r;
}
__device__ __forceinline__ uint32_t smem_u32(const void* p) {
    uint32_t a;
    asm("{ .reg .u64 t; cvta.to.shared.u64 t, %1; cvt.u32.u64 %0, t; }" : "=r"(a) : "l"(p));
    return a;
}
__device__ __forceinline__ void cp16(uint32_t s, const void* g) {
    asm volatile("cp.async.cg.shared.global [%0], [%1], 16;" :: "r"(s), "l"(g));
}
#define CP_COMMIT()  asm volatile("cp.async.commit_group;" ::: "memory")
#define CP_WAIT(n)   asm volatile("cp.async.wait_group %0;" :: "n"(n) : "memory")

__device__ __forceinline__ void mma_tf32(float& c0, float& c1, float& c2, float& c3,
                                         uint32_t a0, uint32_t a1, uint32_t a2, uint32_t a3,
                                         uint32_t b0, uint32_t b1) {
    asm volatile("mma.sync.aligned.m16n8k8.row.col.f32.tf32.tf32.f32 "
        "{%0,%1,%2,%3}, {%4,%5,%6,%7}, {%8,%9}, {%0,%1,%2,%3};"
        : "+f"(c0), "+f"(c1), "+f"(c2), "+f"(c3)
        : "r"(a0), "r"(a1), "r"(a2), "r"(a3), "r"(b0), "r"(b1));
}

// ---------------------------------------------------------------------------
// fp32 -> tf32 with perm16. A float4 covers cols c..c+3 with c = 0,4,8,12
// mod 16 -> dst positions base + 4j + (c&15)/4.
// ---------------------------------------------------------------------------
__device__ __forceinline__ void conv4(const float* __restrict__ src,
                                      uint32_t* __restrict__ dst, int i) {
    float4 v = ((const float4*)src)[i];
    const int c    = i << 2;
    const int base = c & ~15;
    const int off  = (c >> 2) & 3;
    dst[base + off + 0]  = f32_tf32(v.x);
    dst[base + off + 4]  = f32_tf32(v.y);
    dst[base + off + 8]  = f32_tf32(v.z);
    dst[base + off + 12] = f32_tf32(v.w);
}

__global__ void __launch_bounds__(256) conv_x(const float* __restrict__ src,
                                              uint32_t* __restrict__ dst, int n4)
{
    const int i = blockIdx.x * blockDim.x + threadIdx.x;
    if (i < n4) conv4(src, dst, i);
}

__global__ void __launch_bounds__(256) conv_w(const float* __restrict__ s0,
                                              const float* __restrict__ s1,
                                              const float* __restrict__ s2,
                                              const float* __restrict__ s3,
                                              uint32_t* __restrict__ dst)
{
    const int z = blockIdx.y;
    const float* src = (z == 0) ? s0 : (z == 1) ? s1 : (z == 2) ? s2 : s3;
    const int i = blockIdx.x * blockDim.x + threadIdx.x;
    conv4(src, dst + (size_t)z * DIMK * DIMK, i);
}

// ---------------------------------------------------------------------------
// tf32 mma.sync GEMM: CTA 128x128, 256 thr, 8 warps (2M x 4N), warp 64x32.
// 2-stage cp.async, LDS.128 fragment loads (perm16).
// KST=48 => row stride 16 mod 32 words => conflict-free LDS.128 frags.
// ---------------------------------------------------------------------------
#define BM 128
#define BN 128
#define BK 32
#define KST 48
#define STGW ((BM + BN) * KST)           // 12288 words / stage
#define SM_GEMM (2 * STGW * 4)           // 98304 B -> 2 CTAs/SM

__global__ void __launch_bounds__(256, 2) gemm_mma(const uint32_t* __restrict__ A,
                                                   const uint32_t* __restrict__ W0,
                                                   const uint32_t* __restrict__ W1,
                                                   const uint32_t* __restrict__ W2,
                                                   const float* __restrict__ b0p,
                                                   const float* __restrict__ b1p,
                                                   const float* __restrict__ b2p,
                                                   uint32_t* __restrict__ C0,
                                                   uint32_t* __restrict__ C1,
                                                   uint32_t* __restrict__ C2,
                                                   float* __restrict__ Cf,
                                                   int layout)
{
    extern __shared__ __align__(16) uint32_t gsm[];

    const int z = blockIdx.z;
    const uint32_t* W    = (z == 0) ? W0 : (z == 1) ? W1 : W2;
    const float*    bias = (z == 0) ? b0p : (z == 1) ? b1p : b2p;
    uint32_t*       C    = (z == 0) ? C0 : (z == 1) ? C1 : C2;

    const int tid  = threadIdx.x;
    const int wid  = tid >> 5;
    const int lane = tid & 31;
    const int g    = lane >> 2;
    const int t    = lane & 3;
    const int wm   = wid & 1;
    const int wn   = wid >> 1;
    const int m0   = blockIdx.y * BM;
    const int n0   = blockIdx.x * BN;

    const int lrow = tid >> 3;        // 0..31
    const int lc4  = (tid & 7) << 2;  // 0..28 step 4

    const uint32_t smb = smem_u32(gsm);

    float acc[4][4][4];
#pragma unroll
    for (int i = 0; i < 4; i++)
#pragma unroll
        for (int j = 0; j < 4; j++)
#pragma unroll
            for (int r = 0; r < 4; r++) acc[i][j][r] = 0.f;

    const int warpAm = wm * 64;
    const int warpBn = wn * 32;

    const uint32_t* Abase = A + (size_t)(m0 + lrow) * DIMK + lc4;
    const uint32_t* Wbase = W + (size_t)(n0 + lrow) * DIMK + lc4;
    const uint32_t sAoff  = smb + (uint32_t)(lrow * KST + lc4) * 4;
    const uint32_t sBoff  = sAoff + (uint32_t)(BM * KST) * 4;

    // prologue: chunk 0 into stage 0
#pragma unroll
    for (int it = 0; it < 4; it++) {
        const int ro = it << 5;
        cp16(sAoff + (uint32_t)(ro * KST) * 4, Abase + (size_t)ro * DIMK);
        cp16(sBoff + (uint32_t)(ro * KST) * 4, Wbase + (size_t)ro * DIMK);
    }
    CP_COMMIT();

    for (int c = 0; c < 32; c++) {
        CP_WAIT(0);          // chunk c resident
        __syncthreads();     // all warps done reading chunk c-1's stage

        if (c < 31) {
            const uint32_t sb = ((c + 1) & 1) * (uint32_t)(STGW * 4);
            const int k0 = (c + 1) * BK;
#pragma unroll
            for (int it = 0; it < 4; it++) {
                const int ro = it << 5;
                cp16(sAoff + sb + (uint32_t)(ro * KST) * 4, Abase + (size_t)ro * DIMK + k0);
                cp16(sBoff + sb + (uint32_t)(ro * KST) * 4, Wbase + (size_t)ro * DIMK + k0);
            }
            CP_COMMIT();     // overlaps this chunk's MMA
        }

        const uint32_t* As = gsm + (c & 1) * STGW;
        const uint32_t* Bs = As + BM * KST;

#pragma unroll
        for (int h = 0; h < 2; h++) {          // two k16 groups per BK=32
            const int kw = (h << 4) + (t << 2);
            uint4 alo[4], ahi[4], bfr[4];
#pragma unroll
            for (int mt = 0; mt < 4; mt++) {
                const int rb = warpAm + (mt << 4);
                alo[mt] = *(const uint4*)&As[(rb + g    ) * KST + kw];
                ahi[mt] = *(const uint4*)&As[(rb + g + 8) * KST + kw];
            }
#pragma unroll
            for (int nt = 0; nt < 4; nt++) {
                const int nb = warpBn + (nt << 3);
                bfr[nt] = *(const uint4*)&Bs[(nb + g) * KST + kw];
            }
#pragma unroll
            for (int mt = 0; mt < 4; mt++)
#pragma unroll
                for (int nt = 0; nt < 4; nt++) {
                    mma_tf32(acc[mt][nt][0], acc[mt][nt][1],
                             acc[mt][nt][2], acc[mt][nt][3],
                             alo[mt].x, ahi[mt].x, alo[mt].y, ahi[mt].y,
                             bfr[nt].x, bfr[nt].y);
                    mma_tf32(acc[mt][nt][0], acc[mt][nt][1],
                             acc[mt][nt][2], acc[mt][nt][3],
                             alo[mt].z, ahi[mt].z, alo[mt].w, ahi[mt].w,
                             bfr[nt].z, bfr[nt].w);
                }
        }
    }

#pragma unroll
    for (int nt = 0; nt < 4; nt++) {
        const int n = n0 + warpBn + (nt << 3) + (t << 1);
        const float bx = bias[n], by = bias[n + 1];
#pragma unroll
        for (int mt = 0; mt < 4; mt++) {
            const int r0 = m0 + warpAm + (mt << 4) + g;
            const int r1 = r0 + 8;
            const float v00 = acc[mt][nt][0] + bx, v01 = acc[mt][nt][1] + by;
            const float v10 = acc[mt][nt][2] + bx, v11 = acc[mt][nt][3] + by;
            if (layout == 0) {
                *(float2*)(Cf + (size_t)r0 * DIMK + n) = make_float2(v00, v01);
                *(float2*)(Cf + (size_t)r1 * DIMK + n) = make_float2(v10, v11);
            } else {
                const int h_ = n >> 6, d_ = n & 63;
                const int b0_ = r0 >> 12, s0_ = r0 & 4095;
                const int b1_ = r1 >> 12, s1_ = r1 & 4095;
                uint32_t* p0 = C + (((size_t)(b0_ * H + h_)) * SEQ + s0_) * HD;
                uint32_t* p1 = C + (((size_t)(b1_ * H + h_)) * SEQ + s1_) * HD;
                if (z < 2) {   // Q,K: store d perm16
                    const int b16 = d_ & ~15;
                    const int pc0 = b16 | perm16(d_ & 15);
                    const int pc1 = b16 | perm16((d_ & 15) + 1);
                    p0[pc0] = f32_tf32(v00); p0[pc1] = f32_tf32(v01);
                    p1[pc0] = f32_tf32(v10); p1[pc1] = f32_tf32(v11);
                } else {       // V: unpermuted
                    *(uint2*)(p0 + d_) = make_uint2(f32_tf32(v00), f32_tf32(v01));
                    *(uint2*)(p1 + d_) = make_uint2(f32_tf32(v10), f32_tf32(v11));
                }
            }
        }
    }
}

// ---------------------------------------------------------------------------
// Tensorized sliding-window attention. Q fragments hoisted (LDS.128, once);
// K fragments LDS.128 (stride 80, conflict-free); P read back LDS.128
// (stride 72); V scalar reads at rows 16h+t (+0/4/8/12), stride 72 -> 8t
// bank pattern, conflict-free. Ps aliases dead Qs. Boundary-only masking.
// ---------------------------------------------------------------------------
#define QST 72
#define KSTA 80
#define VST 72
#define SM_Q 0
#define SM_K (64 * QST)
#define SM_V (SM_K + 64 * KSTA)
#define SMEM_AMMA ((SM_V + 64 * VST) * 4)   // 57344 B -> 4 CTAs/SM

__global__ void __launch_bounds__(128, 4) attn_mma()
{
    extern __shared__ __align__(16) uint32_t smu[];
    uint32_t* Qs = smu;                  // [64][QST] ; dead after hoist -> Ps
    uint32_t* Ks = smu + SM_K;           // [64][KSTA]
    uint32_t* Vs = smu + SM_V;           // [64][VST]

    const int tid  = threadIdx.x;
    const int w    = tid >> 5;
    const int lane = tid & 31;
    const int g    = lane >> 2;
    const int t    = lane & 3;

    const int qi = blockIdx.x & 63;
    const int h  = (blockIdx.x >> 6) & 15;
    const int b  = blockIdx.x >> 10;
    const int p0 = qi << 6;

    const size_t headoff = ((size_t)(b * H + h)) * SEQ * HD;
    const uint32_t* qbase = g_q + headoff;
    const uint32_t* kbase = g_k + headoff;
    const uint32_t* vbase = g_v + headoff;

    const uint32_t smb = smem_u32(smu);
    const uint32_t Ksb = smb + (uint32_t)SM_K * 4;
    const uint32_t Vsb = smb + (uint32_t)SM_V * 4;

    // stage Q, then hoist this warp's fragments (LDS.128 per k16 group)
#pragma unroll
    for (int it = 0; it < 8; it++) {
        const int u = tid + (it << 7);
        const int row = u >> 4, c4 = (u & 15) << 2;
        cp16(smb + (uint32_t)(row * QST + c4) * 4, qbase + (size_t)(p0 + row) * HD + c4);
    }
    CP_COMMIT(); CP_WAIT(0);
    __syncthreads();

    const int r0 = (w << 4) + g;
    const int q0 = p0 + r0;
    const int q1 = q0 + 8;

    uint4 q4l[4], q4h[4];
#pragma unroll
    for (int hh = 0; hh < 4; hh++) {
        const int kw = (hh << 4) + (t << 2);
        q4l[hh] = *(const uint4*)&Qs[r0 * QST + kw];
        q4h[hh] = *(const uint4*)&Qs[(r0 + 8) * QST + kw];
    }
    __syncthreads();   // Qs now dead -> becomes Ps
    uint32_t* Ps = Qs;

    float O[8][4];
#pragma unroll
    for (int nt = 0; nt < 8; nt++)
#pragma unroll
        for (int r = 0; r < 4; r++) O[nt][r] = 0.f;
    float m0 = -1.0e4f, m1 = -1.0e4f, l0 = 0.f, l1 = 0.f;

    const float SC = 0.125f * 1.44269504f;   // hd^-0.5 * log2(e)

    const int ktlo = (qi >= 8) ? (qi - 8) : 0;
    for (int kt = ktlo; kt <= qi; kt++) {
        const int t0 = kt << 6;
        const bool boundary = (kt == qi) || (kt == qi - 8);

        __syncthreads();   // prior QK reads of Ks + PV reads of Vs complete
#pragma unroll
        for (int it = 0; it < 8; it++) {
            const int u = tid + (it << 7);
            const int row = u >> 4, c4 = (u & 15) << 2;
            cp16(Ksb + (uint32_t)(row * KSTA + c4) * 4, kbase + (size_t)(t0 + row) * HD + c4);
            cp16(Vsb + (uint32_t)(row * VST  + c4) * 4, vbase + (size_t)(t0 + row) * HD + c4);
        }
        CP_COMMIT(); CP_WAIT(0);
        __syncthreads();

        // S = Q K^T  (K fragments LDS.128: two mma k-steps per load)
        float s[8][4];
#pragma unroll
        for (int nt = 0; nt < 8; nt++)
#pragma unroll
            for (int r = 0; r < 4; r++) s[nt][r] = 0.f;

#pragma unroll
        for (int hh = 0; hh < 4; hh++) {
            const int kw = (hh << 4) + (t << 2);
#pragma unroll
            for (int nt = 0; nt < 8; nt++) {
                const uint4 kb = *(const uint4*)&Ks[((nt << 3) + g) * KSTA + kw];
                mma_tf32(s[nt][0], s[nt][1], s[nt][2], s[nt][3],
                         q4l[hh].x, q4h[hh].x, q4l[hh].y, q4h[hh].y, kb.x, kb.y);
                mma_tf32(s[nt][0], s[nt][1], s[nt][2], s[nt][3],
                         q4l[hh].z, q4h[hh].z, q4l[hh].w, q4h[hh].w, kb.z, kb.w);
            }
        }

        // scale (+ mask only on boundary tiles) + online softmax
        float rmax0 = -3.0e4f, rmax1 = -3.0e4f;
        if (boundary) {
#pragma unroll
            for (int nt = 0; nt < 8; nt++) {
                const int c = t0 + (nt << 3) + (t << 1);
                s[nt][0] = ((unsigned)(q0 - c)     < 512u) ? s[nt][0] * SC : -3.0e4f;
                s[nt][1] = ((unsigned)(q0 - c - 1) < 512u) ? s[nt][1] * SC : -3.0e4f;
                s[nt][2] = ((unsigned)(q1 - c)     < 512u) ? s[nt][2] * SC : -3.0e4f;
                s[nt][3] = ((unsigned)(q1 - c - 1) < 512u) ? s[nt][3] * SC : -3.0e4f;
                rmax0 = fmaxf(rmax0, fmaxf(s[nt][0], s[nt][1]));
                rmax1 = fmaxf(rmax1, fmaxf(s[nt][2], s[nt][3]));
            }
        } else {
#pragma unroll
            for (int nt = 0; nt < 8; nt++) {
                s[nt][0] *= SC; s[nt][1] *= SC;
                s[nt][2] *= SC; s[nt][3] *= SC;
                rmax0 = fmaxf(rmax0, fmaxf(s[nt][0], s[nt][1]));
                rmax1 = fmaxf(rmax1, fmaxf(s[nt][2], s[nt][3]));
            }
        }
        rmax0 = fmaxf(rmax0, __shfl_xor_sync(0xffffffffu, rmax0, 1));
        rmax0 = fmaxf(rmax0, __shfl_xor_sync(0xffffffffu, rmax0, 2));
        rmax1 = fmaxf(rmax1, __shfl_xor_sync(0xffffffffu, rmax1, 1));
        rmax1 = fmaxf(rmax1, __shfl_xor_sync(0xffffffffu, rmax1, 2));

        const float mn0 = fmaxf(m0, rmax0);
        const float mn1 = fmaxf(m1, rmax1);
        const float al0 = ex2f(m0 - mn0);
        const float al1 = ex2f(m1 - mn1);
        m0 = mn0; m1 = mn1;

        float rs0 = 0.f, rs1 = 0.f;
#pragma unroll
        for (int nt = 0; nt < 8; nt++) {
            const float p00 = ex2f(s[nt][0] - mn0);
            const float p01 = ex2f(s[nt][1] - mn0);
            const float p10 = ex2f(s[nt][2] - mn1);
            const float p11 = ex2f(s[nt][3] - mn1);
            rs0 += p00 + p01;
            rs1 += p10 + p11;
            // store P at perm16 key positions
            const int w16  = (nt >> 1) << 4;
            const int c16a = ((nt & 1) << 3) + (t << 1);
            const int pa = w16 + perm16(c16a);
            const int pb = w16 + perm16(c16a + 1);
            Ps[r0 * QST + pa]       = f32_tf32(p00);
            Ps[r0 * QST + pb]       = f32_tf32(p01);
            Ps[(r0 + 8) * QST + pa] = f32_tf32(p10);
            Ps[(r0 + 8) * QST + pb] = f32_tf32(p11);
        }
        rs0 += __shfl_xor_sync(0xffffffffu, rs0, 1);
        rs0 += __shfl_xor_sync(0xffffffffu, rs0, 2);
        rs1 += __shfl_xor_sync(0xffffffffu, rs1, 1);
        rs1 += __shfl_xor_sync(0xffffffffu, rs1, 2);

        l0 = l0 * al0 + rs0;
        l1 = l1 * al1 + rs1;
#pragma unroll
        for (int nt = 0; nt < 8; nt++) {
            O[nt][0] *= al0; O[nt][1] *= al0;
            O[nt][2] *= al1; O[nt][3] *= al1;
        }
        __syncwarp();      // Ps rows are warp-private

        // O += P V  (P a-frags LDS.128; V scalar rows 16h+t+{0,4,8,12})
#pragma unroll
        for (int hh = 0; hh < 4; hh++) {
            const int kw = (hh << 4) + (t << 2);
            const uint4 pl = *(const uint4*)&Ps[r0 * QST + kw];
            const uint4 ph = *(const uint4*)&Ps[(r0 + 8) * QST + kw];
            const int vr = (hh << 4) + t;
#pragma unroll
            for (int nt = 0; nt < 8; nt++) {
                const int nc = (nt << 3) + g;
                const uint32_t b0 = Vs[(vr     ) * VST + nc];
                const uint32_t b1 = Vs[(vr +  4) * VST + nc];
                const uint32_t b2 = Vs[(vr +  8) * VST + nc];
                const uint32_t b3 = Vs[(vr + 12) * VST + nc];
                mma_tf32(O[nt][0], O[nt][1], O[nt][2], O[nt][3],
                         pl.x, ph.x, pl.y, ph.y, b0, b1);
                mma_tf32(O[nt][0], O[nt][1], O[nt][2], O[nt][3],
                         pl.z, ph.z, pl.w, ph.w, b2, b3);
            }
        }
    }

    // epilogue: normalize, write d perm16 tf32 u32 (consumed by O-proj)
    const float inv0 = 1.f / l0;
    const float inv1 = 1.f / l1;
    uint32_t* dst0 = g_att + ((size_t)b * SEQ + q0) * DIMK + h * HD;
    uint32_t* dst1 = g_att + ((size_t)b * SEQ + q1) * DIMK + h * HD;
#pragma unroll
    for (int nt = 0; nt < 8; nt++) {
        const int w16  = (nt >> 1) << 4;
        const int c16a = ((nt & 1) << 3) + (t << 1);
        const int pa = w16 + perm16(c16a);
        const int pb = w16 + perm16(c16a + 1);
        dst0[pa] = f32_tf32(O[nt][0] * inv0);
        dst0[pb] = f32_tf32(O[nt][1] * inv0);
        dst1[pa] = f32_tf32(O[nt][2] * inv1);
        dst1[pb] = f32_tf32(O[nt][3] * inv1);
    }
}

// ---------------------------------------------------------------------------
extern "C" void kernel_launch(void* const* d_in, const int* in_sizes, int n_in,
                              void* d_out, int out_size)
{
    const float* x  = (const float*)d_in[0];
    const float* Wq = (const float*)d_in[1];
    const float* bq = (const float*)d_in[2];
    const float* Wk = (const float*)d_in[3];
    const float* bk = (const float*)d_in[4];
    const float* Wv = (const float*)d_in[5];
    const float* bv = (const float*)d_in[6];
    const float* Wo = (const float*)d_in[7];
    const float* bo = (const float*)d_in[8];
    float* out = (float*)d_out;

    uint32_t *qp, *kp, *vp, *ap, *xp, *wp;
    cudaGetSymbolAddress((void**)&qp, g_q);
    cudaGetSymbolAddress((void**)&kp, g_k);
    cudaGetSymbolAddress((void**)&vp, g_v);
    cudaGetSymbolAddress((void**)&ap, g_att);
    cudaGetSymbolAddress((void**)&xp, g_x32);
    cudaGetSymbolAddress((void**)&wp, g_w32);
    uint32_t* w0 = wp;
    uint32_t* w1 = wp + (size_t)DIMK * DIMK;
    uint32_t* w2 = wp + 2 * (size_t)DIMK * DIMK;
    uint32_t* w3 = wp + 3 * (size_t)DIMK * DIMK;

    cudaFuncSetAttribute(gemm_mma,
                         cudaFuncAttributeMaxDynamicSharedMemorySize, SM_GEMM);
    cudaFuncSetAttribute(attn_mma,
                         cudaFuncAttributeMaxDynamicSharedMemorySize, SMEM_AMMA);

    // pre-convert (perm16) x and all weights
    const int nx4 = M_TOT * DIMK / 4;
    const int nw4 = DIMK * DIMK / 4;
    conv_x<<<(nx4 + 255) / 256, 256>>>(x, xp, nx4);
    dim3 gw(nw4 / 256, 4);
    conv_w<<<gw, 256>>>(Wq, Wk, Wv, Wo, wp);

    dim3 gqkv(DIMK / BN, M_TOT / BM, 3);   // fused Q/K/V projections
    gemm_mma<<<gqkv, 256, SM_GEMM>>>(xp, w0, w1, w2, bq, bk, bv,
                                     qp, kp, vp, nullptr, 1);
    attn_mma<<<BSZ * H * (SEQ / 64), 128, SMEM_AMMA>>>();
    dim3 go(DIMK / BN, M_TOT / BM, 1);     // output projection (fp32 out)
    gemm_mma<<<go, 256, SM_GEMM>>>(ap, w3, w3, w3, bo, bo, bo,
                                   nullptr, nullptr, nullptr, out, 0);
}

// round 16
// speedup vs baseline: 1.0805x; 1.0805x over previous
#include <cuda_runtime.h>
#include <cstdint>

#define DIMK 1024
#define BSZ  2
#define SEQ  4096
#define H    16
#define HD   64
#define M_TOT (BSZ * SEQ)   // 8192

// ---------------------------------------------------------------------------
// Scratch (allocation-free). tf32 bit patterns as u32. k-dimension buffers use
// perm8(k) = ((k&3)<<1)|((k&4)>>2) within each 8-group so mma fragment loads
// (cols t, t+4) become adjacent 64-bit loads.  (R13 layout, verified.)
// ---------------------------------------------------------------------------
__device__ uint32_t g_q[(size_t)BSZ * H * SEQ * HD];      // d-permuted
__device__ uint32_t g_k[(size_t)BSZ * H * SEQ * HD];      // d-permuted
__device__ uint32_t g_v[(size_t)BSZ * H * SEQ * HD];      // unpermuted
__device__ uint32_t g_att[(size_t)BSZ * SEQ * DIMK];      // d-permuted
__device__ uint32_t g_x32[(size_t)M_TOT * DIMK];          // k-permuted
__device__ uint32_t g_w32[4][(size_t)DIMK * DIMK];        // k-permuted

__device__ __forceinline__ int perm8(int k) { return ((k & 3) << 1) | ((k & 4) >> 2); }

__device__ __forceinline__ uint32_t f32_tf32(float f) {
    uint32_t r; asm("cvt.rna.tf32.f32 %0, %1;" : "=r"(r) : "f"(f)); return r;
}
__device__ __forceinline__ float ex2f(float x) {
    float r; asm("ex2.approx.f32 %0, %1;" : "=f"(r) : "f"(x)); return r;
}
__device__ __forceinline__ uint32_t smem_u32(const void* p) {
    uint32_t a;
    asm("{ .reg .u64 t; cvta.to.shared.u64 t, %1; cvt.u32.u64 %0, t; }" : "=r"(a) : "l"(p));
    return a;
}
__device__ __forceinline__ void cp16(uint32_t s, const void* g) {
    asm volatile("cp.async.cg.shared.global [%0], [%1], 16;" :: "r"(s), "l"(g));
}
#define CP_COMMIT()  asm volatile("cp.async.commit_group;" ::: "memory")
#define CP_WAIT(n)   asm volatile("cp.async.wait_group %0;" :: "n"(n) : "memory")

__device__ __forceinline__ void mma_tf32(float& c0, float& c1, float& c2, float& c3,
                                         uint32_t a0, uint32_t a1, uint32_t a2, uint32_t a3,
                                         uint32_t b0, uint32_t b1) {
    asm volatile("mma.sync.aligned.m16n8k8.row.col.f32.tf32.tf32.f32 "
        "{%0,%1,%2,%3}, {%4,%5,%6,%7}, {%8,%9}, {%0,%1,%2,%3};"
        : "+f"(c0), "+f"(c1), "+f"(c2), "+f"(c3)
        : "r"(a0), "r"(a1), "r"(a2), "r"(a3), "r"(b0), "r"(b1));
}

// ---------------------------------------------------------------------------
// fp32 -> tf32 with perm8 (R13).
// ---------------------------------------------------------------------------
__device__ __forceinline__ void conv4(const float* __restrict__ src,
                                      uint32_t* __restrict__ dst, int i) {
    float4 v = ((const float4*)src)[i];
    const int c    = i << 2;
    const int base = c & ~7;
    const int off  = (c & 4) ? 1 : 0;
    dst[base + off + 0] = f32_tf32(v.x);
    dst[base + off + 2] = f32_tf32(v.y);
    dst[base + off + 4] = f32_tf32(v.z);
    dst[base + off + 6] = f32_tf32(v.w);
}

__global__ void __launch_bounds__(256) conv_x(const float* __restrict__ src,
                                              uint32_t* __restrict__ dst, int n4)
{
    const int i = blockIdx.x * blockDim.x + threadIdx.x;
    if (i < n4) conv4(src, dst, i);
}

__global__ void __launch_bounds__(256) conv_w(const float* __restrict__ s0,
                                              const float* __restrict__ s1,
                                              const float* __restrict__ s2,
                                              const float* __restrict__ s3,
                                              uint32_t* __restrict__ dst)
{
    const int z = blockIdx.y;
    const float* src = (z == 0) ? s0 : (z == 1) ? s1 : (z == 2) ? s2 : s3;
    const int i = blockIdx.x * blockDim.x + threadIdx.x;
    conv4(src, dst + (size_t)z * DIMK * DIMK, i);
}

// ---------------------------------------------------------------------------
// tf32 mma.sync GEMM — EXACT R13 config (proven): CTA 128x128, 256 thr,
// 8 warps (2M x 4N), warp 64x32, 2-stage cp.async, LDS.64 frags, KST=40.
// ---------------------------------------------------------------------------
#define BM 128
#define BN 128
#define BK 32
#define KST 40
#define STGW ((BM + BN) * KST)           // 10240 words / stage
#define SM_GEMM (2 * STGW * 4)           // 81920 B -> 2 CTAs/SM

__global__ void __launch_bounds__(256, 2) gemm_mma(const uint32_t* __restrict__ A,
                                                   const uint32_t* __restrict__ W0,
                                                   const uint32_t* __restrict__ W1,
                                                   const uint32_t* __restrict__ W2,
                                                   const float* __restrict__ b0p,
                                                   const float* __restrict__ b1p,
                                                   const float* __restrict__ b2p,
                                                   uint32_t* __restrict__ C0,
                                                   uint32_t* __restrict__ C1,
                                                   uint32_t* __restrict__ C2,
                                                   float* __restrict__ Cf,
                                                   int layout)
{
    extern __shared__ __align__(16) uint32_t gsm[];

    const int z = blockIdx.z;
    const uint32_t* W    = (z == 0) ? W0 : (z == 1) ? W1 : W2;
    const float*    bias = (z == 0) ? b0p : (z == 1) ? b1p : b2p;
    uint32_t*       C    = (z == 0) ? C0 : (z == 1) ? C1 : C2;

    const int tid  = threadIdx.x;
    const int wid  = tid >> 5;
    const int lane = tid & 31;
    const int g    = lane >> 2;
    const int t    = lane & 3;
    const int wm   = wid & 1;
    const int wn   = wid >> 1;
    const int m0   = blockIdx.y * BM;
    const int n0   = blockIdx.x * BN;

    const int lrow = tid >> 3;        // 0..31
    const int lc4  = (tid & 7) << 2;  // 0..28 step 4

    const uint32_t smb = smem_u32(gsm);

    float acc[4][4][4];
#pragma unroll
    for (int i = 0; i < 4; i++)
#pragma unroll
        for (int j = 0; j < 4; j++)
#pragma unroll
            for (int r = 0; r < 4; r++) acc[i][j][r] = 0.f;

    const int warpAm = wm * 64;
    const int warpBn = wn * 32;

    const uint32_t* Abase = A + (size_t)(m0 + lrow) * DIMK + lc4;
    const uint32_t* Wbase = W + (size_t)(n0 + lrow) * DIMK + lc4;
    const uint32_t sAoff  = smb + (uint32_t)(lrow * KST + lc4) * 4;
    const uint32_t sBoff  = sAoff + (uint32_t)(BM * KST) * 4;

#pragma unroll
    for (int it = 0; it < 4; it++) {
        const int ro = it << 5;
        cp16(sAoff + (uint32_t)(ro * KST) * 4, Abase + (size_t)ro * DIMK);
        cp16(sBoff + (uint32_t)(ro * KST) * 4, Wbase + (size_t)ro * DIMK);
    }
    CP_COMMIT();

    for (int c = 0; c < 32; c++) {
        CP_WAIT(0);
        __syncthreads();

        if (c < 31) {
            const uint32_t sb = ((c + 1) & 1) * (uint32_t)(STGW * 4);
            const int k0 = (c + 1) * BK;
#pragma unroll
            for (int it = 0; it < 4; it++) {
                const int ro = it << 5;
                cp16(sAoff + sb + (uint32_t)(ro * KST) * 4, Abase + (size_t)ro * DIMK + k0);
                cp16(sBoff + sb + (uint32_t)(ro * KST) * 4, Wbase + (size_t)ro * DIMK + k0);
            }
            CP_COMMIT();
        }

        const uint32_t* As = gsm + (c & 1) * STGW;
        const uint32_t* Bs = As + BM * KST;

#pragma unroll
        for (int ks = 0; ks < 4; ks++) {
            const int kk = (ks << 3) + (t << 1);
            uint2 al[4], ah[4], bb[4];
#pragma unroll
            for (int mt = 0; mt < 4; mt++) {
                const int rb = warpAm + (mt << 4);
                al[mt] = *(const uint2*)&As[(rb + g    ) * KST + kk];
                ah[mt] = *(const uint2*)&As[(rb + g + 8) * KST + kk];
            }
#pragma unroll
            for (int nt = 0; nt < 4; nt++) {
                const int nb = warpBn + (nt << 3);
                bb[nt] = *(const uint2*)&Bs[(nb + g) * KST + kk];
            }
#pragma unroll
            for (int mt = 0; mt < 4; mt++)
#pragma unroll
                for (int nt = 0; nt < 4; nt++)
                    mma_tf32(acc[mt][nt][0], acc[mt][nt][1],
                             acc[mt][nt][2], acc[mt][nt][3],
                             al[mt].x, ah[mt].x, al[mt].y, ah[mt].y,
                             bb[nt].x, bb[nt].y);
        }
    }

#pragma unroll
    for (int nt = 0; nt < 4; nt++) {
        const int n = n0 + warpBn + (nt << 3) + (t << 1);
        const float bx = bias[n], by = bias[n + 1];
#pragma unroll
        for (int mt = 0; mt < 4; mt++) {
            const int r0 = m0 + warpAm + (mt << 4) + g;
            const int r1 = r0 + 8;
            const float v00 = acc[mt][nt][0] + bx, v01 = acc[mt][nt][1] + by;
            const float v10 = acc[mt][nt][2] + bx, v11 = acc[mt][nt][3] + by;
            if (layout == 0) {
                *(float2*)(Cf + (size_t)r0 * DIMK + n) = make_float2(v00, v01);
                *(float2*)(Cf + (size_t)r1 * DIMK + n) = make_float2(v10, v11);
            } else {
                const int h_ = n >> 6, d_ = n & 63;
                const int b0_ = r0 >> 12, s0_ = r0 & 4095;
                const int b1_ = r1 >> 12, s1_ = r1 & 4095;
                uint32_t* p0 = C + (((size_t)(b0_ * H + h_)) * SEQ + s0_) * HD;
                uint32_t* p1 = C + (((size_t)(b1_ * H + h_)) * SEQ + s1_) * HD;
                if (z < 2) {
                    const int pc0 = (d_ & ~7) | perm8(d_ & 7);
                    const int pc1 = (d_ & ~7) | perm8((d_ & 7) + 1);
                    p0[pc0] = f32_tf32(v00); p0[pc1] = f32_tf32(v01);
                    p1[pc0] = f32_tf32(v10); p1[pc1] = f32_tf32(v11);
                } else {
                    *(uint2*)(p0 + d_) = make_uint2(f32_tf32(v00), f32_tf32(v01));
                    *(uint2*)(p1 + d_) = make_uint2(f32_tf32(v10), f32_tf32(v11));
                }
            }
        }
    }
}

// ---------------------------------------------------------------------------
// Tensorized sliding-window attention, 128-query CTA (256 thr, 8 warps).
// Warps 0-3 own rows 0-63 (tiles [qt0-8, qt0]), warps 4-7 rows 64-127
// (tiles [qt0-7, qt0+1]) — each half's skipped tile is provably fully masked.
// K/V double-buffered, single barrier per tile (gemm pattern). Per-warp
// fragment/softmax/mask math identical to R13 (bit-exact).
// ---------------------------------------------------------------------------
#define AST 72
#define VST 68
#define SM_P 0                         // Ps/Qs: [128][AST]
#define SM_K (128 * AST)               // Kbuf: 2 x [64][AST]
#define SM_V (SM_K + 2 * 64 * AST)     // Vbuf: 2 x [64][VST]
#define SMEM_AMMA ((SM_V + 2 * 64 * VST) * 4)   // 106496 B -> 2 CTAs/SM

__global__ void __launch_bounds__(256, 2) attn_mma()
{
    extern __shared__ __align__(16) uint32_t smu[];
    uint32_t* Qs = smu;                   // [128][AST]; dead after hoist -> Ps
    uint32_t* Kb = smu + SM_K;            // 2 x [64][AST]
    uint32_t* Vb = smu + SM_V;            // 2 x [64][VST]

    const int tid  = threadIdx.x;
    const int w    = tid >> 5;
    const int lane = tid & 31;
    const int g    = lane >> 2;
    const int t    = lane & 3;
    const int half = w >> 2;

    const int qi2 = blockIdx.x & 31;          // 32 query blocks of 128
    const int h   = (blockIdx.x >> 5) & 15;
    const int b   = blockIdx.x >> 9;
    const int p0  = qi2 << 7;
    const int qt0 = qi2 << 1;                 // first key-tile index of diag pair

    const size_t headoff = ((size_t)(b * H + h)) * SEQ * HD;
    const uint32_t* qbase = g_q + headoff;
    const uint32_t* kbase = g_k + headoff;
    const uint32_t* vbase = g_v + headoff;

    const uint32_t smb = smem_u32(smu);
    const uint32_t Kba = smb + (uint32_t)SM_K * 4;
    const uint32_t Vba = smb + (uint32_t)SM_V * 4;

    // stage Q (128 rows), hoist this warp's fragments
#pragma unroll
    for (int it = 0; it < 8; it++) {
        const int u = tid + (it << 8);
        const int row = u >> 4, c4 = (u & 15) << 2;
        cp16(smb + (uint32_t)(row * AST + c4) * 4, qbase + (size_t)(p0 + row) * HD + c4);
    }
    CP_COMMIT(); CP_WAIT(0);
    __syncthreads();

    const int wr = (w << 4) + g;        // this thread's P-row (0..127)
    const int q0 = p0 + wr;
    const int q1 = q0 + 8;
    const int pc0 = perm8(t << 1);
    const int pc1 = perm8((t << 1) + 1);

    uint2 qfl[8], qfh[8];
#pragma unroll
    for (int ks = 0; ks < 8; ks++) {
        const int kk = (ks << 3) + (t << 1);
        qfl[ks] = *(const uint2*)&Qs[wr * AST + kk];
        qfh[ks] = *(const uint2*)&Qs[(wr + 8) * AST + kk];
    }
    __syncthreads();   // Qs dead -> Ps
    uint32_t* Ps = Qs;

    float O[8][4];
#pragma unroll
    for (int nt = 0; nt < 8; nt++)
#pragma unroll
        for (int r = 0; r < 4; r++) O[nt][r] = 0.f;
    float m0 = -1.0e4f, m1 = -1.0e4f, l0 = 0.f, l1 = 0.f;

    const float SC = 0.125f * 1.44269504f;   // hd^-0.5 * log2(e)

    const int ktlo = (qt0 >= 8) ? (qt0 - 8) : 0;
    const int kthi = qt0 + 1;

    // prologue: stage first tile into buffer (ktlo & 1)
    {
        const int t0 = ktlo << 6;
        const uint32_t kb0 = Kba + (uint32_t)((ktlo & 1) * 64 * AST) * 4;
        const uint32_t vb0 = Vba + (uint32_t)((ktlo & 1) * 64 * VST) * 4;
#pragma unroll
        for (int it = 0; it < 4; it++) {
            const int u = tid + (it << 8);
            const int row = u >> 4, c4 = (u & 15) << 2;
            const int pr = (row & ~7) | perm8(row & 7);
            cp16(kb0 + (uint32_t)(row * AST + c4) * 4, kbase + (size_t)(t0 + row) * HD + c4);
            cp16(vb0 + (uint32_t)(pr  * VST + c4) * 4, vbase + (size_t)(t0 + row) * HD + c4);
        }
        CP_COMMIT();
    }

    for (int kt = ktlo; kt <= kthi; kt++) {
        CP_WAIT(0);        // tile kt resident
        __syncthreads();   // all warps done with buffer (kt+1)&1 (used at kt-1)

        if (kt < kthi) {   // prefetch kt+1 (overlaps this tile's compute)
            const int t0n = (kt + 1) << 6;
            const uint32_t kbn = Kba + (uint32_t)(((kt + 1) & 1) * 64 * AST) * 4;
            const uint32_t vbn = Vba + (uint32_t)(((kt + 1) & 1) * 64 * VST) * 4;
#pragma unroll
            for (int it = 0; it < 4; it++) {
                const int u = tid + (it << 8);
                const int row = u >> 4, c4 = (u & 15) << 2;
                const int pr = (row & ~7) | perm8(row & 7);
                cp16(kbn + (uint32_t)(row * AST + c4) * 4, kbase + (size_t)(t0n + row) * HD + c4);
                cp16(vbn + (uint32_t)(pr  * VST + c4) * 4, vbase + (size_t)(t0n + row) * HD + c4);
            }
            CP_COMMIT();
        }

        // warp-half participation: other half's extreme tile is fully masked
        const bool part = half ? (kt >= qt0 - 7) : (kt <= qt0);
        if (!part) continue;

        const uint32_t* Ks = Kb + (kt & 1) * 64 * AST;
        const uint32_t* Vs = Vb + (kt & 1) * 64 * VST;
        const int t0 = kt << 6;
        const bool boundary = half ? (kt == qt0 + 1 || kt == qt0 - 7)
                                   : (kt == qt0     || kt == qt0 - 8);

        // S = Q K^T
        float s[8][4];
#pragma unroll
        for (int nt = 0; nt < 8; nt++)
#pragma unroll
            for (int r = 0; r < 4; r++) s[nt][r] = 0.f;

#pragma unroll
        for (int ks = 0; ks < 8; ks++) {
            const int kk = (ks << 3) + (t << 1);
#pragma unroll
            for (int nt = 0; nt < 8; nt++) {
                const uint2 kb = *(const uint2*)&Ks[((nt << 3) + g) * AST + kk];
                mma_tf32(s[nt][0], s[nt][1], s[nt][2], s[nt][3],
                         qfl[ks].x, qfh[ks].x, qfl[ks].y, qfh[ks].y, kb.x, kb.y);
            }
        }

        // scale (+ mask on boundary tiles) + online softmax
        float rmax0 = -3.0e4f, rmax1 = -3.0e4f;
        if (boundary) {
#pragma unroll
            for (int nt = 0; nt < 8; nt++) {
                const int c = t0 + (nt << 3) + (t << 1);
                s[nt][0] = ((unsigned)(q0 - c)     < 512u) ? s[nt][0] * SC : -3.0e4f;
                s[nt][1] = ((unsigned)(q0 - c - 1) < 512u) ? s[nt][1] * SC : -3.0e4f;
                s[nt][2] = ((unsigned)(q1 - c)     < 512u) ? s[nt][2] * SC : -3.0e4f;
                s[nt][3] = ((unsigned)(q1 - c - 1) < 512u) ? s[nt][3] * SC : -3.0e4f;
                rmax0 = fmaxf(rmax0, fmaxf(s[nt][0], s[nt][1]));
                rmax1 = fmaxf(rmax1, fmaxf(s[nt][2], s[nt][3]));
            }
        } else {
#pragma unroll
            for (int nt = 0; nt < 8; nt++) {
                s[nt][0] *= SC; s[nt][1] *= SC;
                s[nt][2] *= SC; s[nt][3] *= SC;
                rmax0 = fmaxf(rmax0, fmaxf(s[nt][0], s[nt][1]));
                rmax1 = fmaxf(rmax1, fmaxf(s[nt][2], s[nt][3]));
            }
        }
        rmax0 = fmaxf(rmax0, __shfl_xor_sync(0xffffffffu, rmax0, 1));
        rmax0 = fmaxf(rmax0, __shfl_xor_sync(0xffffffffu, rmax0, 2));
        rmax1 = fmaxf(rmax1, __shfl_xor_sync(0xffffffffu, rmax1, 1));
        rmax1 = fmaxf(rmax1, __shfl_xor_sync(0xffffffffu, rmax1, 2));

        const float mn0 = fmaxf(m0, rmax0);
        const float mn1 = fmaxf(m1, rmax1);
        const float al0 = ex2f(m0 - mn0);
        const float al1 = ex2f(m1 - mn1);
        m0 = mn0; m1 = mn1;

        float rs0 = 0.f, rs1 = 0.f;
#pragma unroll
        for (int nt = 0; nt < 8; nt++) {
            const float p00 = ex2f(s[nt][0] - mn0);
            const float p01 = ex2f(s[nt][1] - mn0);
            const float p10 = ex2f(s[nt][2] - mn1);
            const float p11 = ex2f(s[nt][3] - mn1);
            rs0 += p00 + p01;
            rs1 += p10 + p11;
            const int nb = nt << 3;
            Ps[wr * AST + nb + pc0]       = f32_tf32(p00);
            Ps[wr * AST + nb + pc1]       = f32_tf32(p01);
            Ps[(wr + 8) * AST + nb + pc0] = f32_tf32(p10);
            Ps[(wr + 8) * AST + nb + pc1] = f32_tf32(p11);
        }
        rs0 += __shfl_xor_sync(0xffffffffu, rs0, 1);
        rs0 += __shfl_xor_sync(0xffffffffu, rs0, 2);
        rs1 += __shfl_xor_sync(0xffffffffu, rs1, 1);
        rs1 += __shfl_xor_sync(0xffffffffu, rs1, 2);

        l0 = l0 * al0 + rs0;
        l1 = l1 * al1 + rs1;
#pragma unroll
        for (int nt = 0; nt < 8; nt++) {
            O[nt][0] *= al0; O[nt][1] *= al0;
            O[nt][2] *= al1; O[nt][3] *= al1;
        }
        __syncwarp();      // Ps rows are warp-private

        // O += P V
#pragma unroll
        for (int ks = 0; ks < 8; ks++) {
            const int kk = (ks << 3) + (t << 1);
            const uint2 pl = *(const uint2*)&Ps[wr * AST + kk];
            const uint2 ph = *(const uint2*)&Ps[(wr + 8) * AST + kk];
#pragma unroll
            for (int nt = 0; nt < 8; nt++) {
                const uint32_t b0 = Vs[kk * VST + (nt << 3) + g];
                const uint32_t b1 = Vs[(kk + 1) * VST + (nt << 3) + g];
                mma_tf32(O[nt][0], O[nt][1], O[nt][2], O[nt][3],
                         pl.x, ph.x, pl.y, ph.y, b0, b1);
            }
        }
    }

    // epilogue: normalize, write d-permuted tf32 u32 (consumed by O-proj)
    const float inv0 = 1.f / l0;
    const float inv1 = 1.f / l1;
    uint32_t* dst0 = g_att + ((size_t)b * SEQ + q0) * DIMK + h * HD;
    uint32_t* dst1 = g_att + ((size_t)b * SEQ + q1) * DIMK + h * HD;
#pragma unroll
    for (int nt = 0; nt < 8; nt++) {
        const int nb = nt << 3;
        dst0[nb + pc0] = f32_tf32(O[nt][0] * inv0);
        dst0[nb + pc1] = f32_tf32(O[nt][1] * inv0);
        dst1[nb + pc0] = f32_tf32(O[nt][2] * inv1);
        dst1[nb + pc1] = f32_tf32(O[nt][3] * inv1);
    }
}

// ---------------------------------------------------------------------------
extern "C" void kernel_launch(void* const* d_in, const int* in_sizes, int n_in,
                              void* d_out, int out_size)
{
    const float* x  = (const float*)d_in[0];
    const float* Wq = (const float*)d_in[1];
    const float* bq = (const float*)d_in[2];
    const float* Wk = (const float*)d_in[3];
    const float* bk = (const float*)d_in[4];
    const float* Wv = (const float*)d_in[5];
    const float* bv = (const float*)d_in[6];
    const float* Wo = (const float*)d_in[7];
    const float* bo = (const float*)d_in[8];
    float* out = (float*)d_out;

    uint32_t *qp, *kp, *vp, *ap, *xp, *wp;
    cudaGetSymbolAddress((void**)&qp, g_q);
    cudaGetSymbolAddress((void**)&kp, g_k);
    cudaGetSymbolAddress((void**)&vp, g_v);
    cudaGetSymbolAddress((void**)&ap, g_att);
    cudaGetSymbolAddress((void**)&xp, g_x32);
    cudaGetSymbolAddress((void**)&wp, g_w32);
    uint32_t* w0 = wp;
    uint32_t* w1 = wp + (size_t)DIMK * DIMK;
    uint32_t* w2 = wp + 2 * (size_t)DIMK * DIMK;
    uint32_t* w3 = wp + 3 * (size_t)DIMK * DIMK;

    cudaFuncSetAttribute(gemm_mma,
                         cudaFuncAttributeMaxDynamicSharedMemorySize, SM_GEMM);
    cudaFuncSetAttribute(attn_mma,
                         cudaFuncAttributeMaxDynamicSharedMemorySize, SMEM_AMMA);

    // pre-convert (perm8) x and all weights
    const int nx4 = M_TOT * DIMK / 4;
    const int nw4 = DIMK * DIMK / 4;
    conv_x<<<(nx4 + 255) / 256, 256>>>(x, xp, nx4);
    dim3 gw(nw4 / 256, 4);
    conv_w<<<gw, 256>>>(Wq, Wk, Wv, Wo, wp);

    dim3 gqkv(DIMK / BN, M_TOT / BM, 3);   // fused Q/K/V projections
    gemm_mma<<<gqkv, 256, SM_GEMM>>>(xp, w0, w1, w2, bq, bk, bv,
                                     qp, kp, vp, nullptr, 1);
    attn_mma<<<BSZ * H * (SEQ / 128), 256, SMEM_AMMA>>>();   // 1024 CTAs
    dim3 go(DIMK / BN, M_TOT / BM, 1);     // output projection (fp32 out)
    gemm_mma<<<go, 256, SM_GEMM>>>(ap, w3, w3, w3, bo, bo, bo,
                                   nullptr, nullptr, nullptr, out, 0);
}